// round 2
// baseline (speedup 1.0000x reference)
#include <cuda_runtime.h>
#include <cstdint>

// Problem-size upper bounds (fixed by the dataset)
static constexpr int NN = 50048;

// Scratch (device globals: allocation-free per harness rules)
__device__ __align__(16) float g_x[(long long)NN * 128];  // mlp output [N,128]
__device__ float4 g_h1[NN];   // per-node logits, conv1 (4 heads)
__device__ float4 g_h2[NN];   // per-node logits, conv2 (4 heads)

// ---------------------------------------------------------------------------
// Kernel 1: X = feat @ W_mlp + b_mlp ; OUT = eps * X   (classic SGEMM tiling)
// BM=128, BN=128, BK=16, 256 threads, 8x8 micro-tile per thread
// ---------------------------------------------------------------------------
__global__ __launch_bounds__(256) void gemm_mlp_kernel(
    const float* __restrict__ A,     // feat [N,256]
    const float* __restrict__ B,     // W_mlp [256,128] row-major (K x N)
    const float* __restrict__ bias,  // [128]
    const float* __restrict__ eps,   // [1]
    float* __restrict__ OUT,         // [N,128]
    int N)
{
    __shared__ float As[16][128];  // transposed A tile: As[k][m]
    __shared__ float Bs[16][128];  // Bs[k][n]

    const int tid  = threadIdx.x;
    const int brow = blockIdx.x * 128;
    const int tcol = (tid & 15) * 8;   // 0..120
    const int trow = (tid >> 4) * 8;   // 0..120

    float acc[8][8];
#pragma unroll
    for (int i = 0; i < 8; i++)
#pragma unroll
        for (int j = 0; j < 8; j++) acc[i][j] = 0.f;

    for (int k0 = 0; k0 < 256; k0 += 16) {
        // Load A tile (128 rows x 16 k), store transposed.  2 float4 / thread.
#pragma unroll
        for (int i = 0; i < 2; i++) {
            int idx = tid * 2 + i;          // 0..511
            int r   = idx >> 2;             // 0..127
            int c4  = (idx & 3) * 4;        // 0,4,8,12
            int gr  = brow + r;
            float4 v = make_float4(0.f, 0.f, 0.f, 0.f);
            if (gr < N) v = *(const float4*)(A + (long long)gr * 256 + k0 + c4);
            As[c4 + 0][r] = v.x;
            As[c4 + 1][r] = v.y;
            As[c4 + 2][r] = v.z;
            As[c4 + 3][r] = v.w;
        }
        // Load B tile (16 k x 128 n).  2 float4 / thread, coalesced.
#pragma unroll
        for (int i = 0; i < 2; i++) {
            int idx = tid * 2 + i;          // 0..511
            int r   = idx >> 5;             // 0..15
            int c4  = (idx & 31) * 4;       // 0..124
            *(float4*)&Bs[r][c4] = *(const float4*)(B + (long long)(k0 + r) * 128 + c4);
        }
        __syncthreads();

#pragma unroll
        for (int k = 0; k < 16; k++) {
            float am[8], bn[8];
#pragma unroll
            for (int i = 0; i < 8; i++) am[i] = As[k][trow + i];
#pragma unroll
            for (int j = 0; j < 8; j++) bn[j] = Bs[k][tcol + j];
#pragma unroll
            for (int i = 0; i < 8; i++)
#pragma unroll
                for (int j = 0; j < 8; j++)
                    acc[i][j] = fmaf(am[i], bn[j], acc[i][j]);
        }
        __syncthreads();
    }

    const float e0 = eps[0];
#pragma unroll
    for (int i = 0; i < 8; i++) {
        int gr = brow + trow + i;
        if (gr < N) {
#pragma unroll
            for (int j = 0; j < 8; j += 4) {
                float4 v;
                v.x = acc[i][j + 0] + bias[tcol + j + 0];
                v.y = acc[i][j + 1] + bias[tcol + j + 1];
                v.z = acc[i][j + 2] + bias[tcol + j + 2];
                v.w = acc[i][j + 3] + bias[tcol + j + 3];
                *(float4*)(g_x + (long long)gr * 128 + tcol + j) = v;
                float4 o = make_float4(e0 * v.x, e0 * v.y, e0 * v.z, e0 * v.w);
                *(float4*)(OUT + (long long)gr * 128 + tcol + j) = o;
            }
        }
    }
}

// ---------------------------------------------------------------------------
// Kernel 2: h1 = feat @ W1^T + b1, h2 = feat @ W2^T + b2   (one warp / node)
// ---------------------------------------------------------------------------
__global__ __launch_bounds__(256) void h_kernel(
    const float* __restrict__ feat,
    const float* __restrict__ W1, const float* __restrict__ b1,
    const float* __restrict__ W2, const float* __restrict__ b2,
    int N)
{
    int warp = (blockIdx.x * blockDim.x + threadIdx.x) >> 5;
    if (warp >= N) return;
    int lane = threadIdx.x & 31;

    float a[4] = {0.f, 0.f, 0.f, 0.f};
    float b[4] = {0.f, 0.f, 0.f, 0.f};
    const float* frow = feat + (long long)warp * 256;
#pragma unroll
    for (int kk = 0; kk < 8; kk++) {
        int k   = lane + kk * 32;
        float f = frow[k];
#pragma unroll
        for (int j = 0; j < 4; j++) {
            a[j] = fmaf(f, __ldg(W1 + j * 256 + k), a[j]);
            b[j] = fmaf(f, __ldg(W2 + j * 256 + k), b[j]);
        }
    }
#pragma unroll
    for (int off = 16; off; off >>= 1) {
#pragma unroll
        for (int j = 0; j < 4; j++) {
            a[j] += __shfl_xor_sync(0xFFFFFFFFu, a[j], off);
            b[j] += __shfl_xor_sync(0xFFFFFFFFu, b[j], off);
        }
    }
    if (lane == 0) {
        g_h1[warp] = make_float4(a[0] + b1[0], a[1] + b1[1], a[2] + b1[2], a[3] + b1[3]);
        g_h2[warp] = make_float4(b[0] + b2[0], b[1] + b2[1], b[2] + b2[2], b[3] + b2[3]);
    }
}

// ---------------------------------------------------------------------------
// Kernel 3: edge scatter.  One warp per edge.
//   v[h] = relu(h1[src][h] + h2[dst][h])      (4 heads)
//   out[src][h*32+f] += v[h] * x[dst][h*32+f] (128 floats, red.v4, zero-skip)
// ---------------------------------------------------------------------------
__global__ __launch_bounds__(256) void edge_kernel(
    const int* __restrict__ ei,  // [2,E]  (int32: JAX x64 is disabled)
    float* __restrict__ OUT,
    int E)
{
    int e = blockIdx.x * 8 + (threadIdx.x >> 5);
    if (e >= E) return;
    int lane = threadIdx.x & 31;

    int src = ei[e];
    int dst = ei[E + e];

    const float4 ha = g_h1[src];  // broadcast across warp
    const float4 hb = g_h2[dst];

    int h = lane >> 3;  // head for this lane's 4-float chunk
    float v = (h < 2) ? (h == 0 ? ha.x + hb.x : ha.y + hb.y)
                      : (h == 2 ? ha.z + hb.z : ha.w + hb.w);

    if (v > 0.f) {  // relu zero-skip: drop gather + atomic entirely
        int j = lane * 4;
        float4 xv = *(const float4*)(g_x + (long long)dst * 128 + j);
        float* p  = OUT + (long long)src * 128 + j;
        asm volatile("red.global.add.v4.f32 [%0], {%1,%2,%3,%4};"
                     :: "l"(p), "f"(v * xv.x), "f"(v * xv.y),
                        "f"(v * xv.z), "f"(v * xv.w)
                     : "memory");
    }
}

// ---------------------------------------------------------------------------
extern "C" void kernel_launch(void* const* d_in, const int* in_sizes, int n_in,
                              void* d_out, int out_size)
{
    const float* feat  = (const float*)d_in[0];
    const int*   ei    = (const int*)d_in[1];
    const float* W_mlp = (const float*)d_in[2];
    const float* b_mlp = (const float*)d_in[3];
    const float* W1    = (const float*)d_in[4];
    const float* b1    = (const float*)d_in[5];
    const float* W2    = (const float*)d_in[6];
    const float* b2    = (const float*)d_in[7];
    const float* eps   = (const float*)d_in[8];

    const int N = in_sizes[0] / 256;
    const int E = in_sizes[1] / 2;
    float* out = (float*)d_out;

    // 1) x = feat@W_mlp+b ; out = eps*x   (also materializes g_x)
    gemm_mlp_kernel<<<(N + 127) / 128, 256>>>(feat, W_mlp, b_mlp, eps, out, N);
    // 2) per-node attention logits
    h_kernel<<<(N + 7) / 8, 256>>>(feat, W1, b1, W2, b2, N);
    // 3) edge gather-weight-scatter (atomic vector reductions into out)
    edge_kernel<<<(E + 7) / 8, 256>>>(ei, out, E);
}

// round 3
// speedup vs baseline: 1.0473x; 1.0473x over previous
#include <cuda_runtime.h>
#include <cstdint>

// Problem sizes (fixed by the dataset; bounds for static scratch)
static constexpr int NN = 50000;
static constexpr int EE = 800000;

// Scratch (device globals: allocation-free per harness rules)
__device__ __align__(16) float g_x[(long long)NN * 128];  // mlp output [N,128]
__device__ float4 g_h1[NN];        // per-node logits, conv1 (4 heads)
__device__ float4 g_h2[NN];        // per-node logits, conv2 (4 heads)
__device__ int    g_cnt[NN];       // per-src degree
__device__ int    g_off[NN + 1];   // CSR row offsets
__device__ int    g_cur[NN];       // scatter cursors
__device__ int    g_sdst[EE];      // dst sorted by src

// ---------------------------------------------------------------------------
// Kernel 1: X = feat @ W_mlp + b_mlp  (SGEMM, packed f32x2 FMA — Blackwell FFMA2)
// BM=128, BN=128, BK=16, 256 threads, 8x8 micro-tile per thread
// ---------------------------------------------------------------------------
__global__ __launch_bounds__(256) void gemm_mlp_kernel(
    const float* __restrict__ A,     // feat [N,256]
    const float* __restrict__ B,     // W_mlp [256,128] row-major (K x N)
    const float* __restrict__ bias,  // [128]
    int N)
{
    __shared__ float As[16][128];  // transposed A tile: As[k][m]
    __shared__ float Bs[16][128];  // Bs[k][n]

    const int tid  = threadIdx.x;
    const int brow = blockIdx.x * 128;
    const int tcol = (tid & 15) * 8;   // 0..120
    const int trow = (tid >> 4) * 8;   // 0..120

    // 8x8 accumulators as 8x4 packed f32x2
    unsigned long long acc2[8][4];
#pragma unroll
    for (int i = 0; i < 8; i++)
#pragma unroll
        for (int j = 0; j < 4; j++) acc2[i][j] = 0ull;

    for (int k0 = 0; k0 < 256; k0 += 16) {
#pragma unroll
        for (int i = 0; i < 2; i++) {
            int idx = tid * 2 + i;          // 0..511
            int r   = idx >> 2;             // 0..127
            int c4  = (idx & 3) * 4;        // 0,4,8,12
            int gr  = brow + r;
            float4 v = make_float4(0.f, 0.f, 0.f, 0.f);
            if (gr < N) v = *(const float4*)(A + (long long)gr * 256 + k0 + c4);
            As[c4 + 0][r] = v.x;
            As[c4 + 1][r] = v.y;
            As[c4 + 2][r] = v.z;
            As[c4 + 3][r] = v.w;
        }
#pragma unroll
        for (int i = 0; i < 2; i++) {
            int idx = tid * 2 + i;          // 0..511
            int r   = idx >> 5;             // 0..15
            int c4  = (idx & 31) * 4;       // 0..124
            *(float4*)&Bs[r][c4] = *(const float4*)(B + (long long)(k0 + r) * 128 + c4);
        }
        __syncthreads();

#pragma unroll
        for (int k = 0; k < 16; k++) {
            // B fragment: 8 floats = 4 packed f32x2
            unsigned long long bn2[4];
            {
                float4 b0 = *(const float4*)&Bs[k][tcol];
                float4 b1 = *(const float4*)&Bs[k][tcol + 4];
                float2 p;
                p = make_float2(b0.x, b0.y); bn2[0] = *reinterpret_cast<unsigned long long*>(&p);
                p = make_float2(b0.z, b0.w); bn2[1] = *reinterpret_cast<unsigned long long*>(&p);
                p = make_float2(b1.x, b1.y); bn2[2] = *reinterpret_cast<unsigned long long*>(&p);
                p = make_float2(b1.z, b1.w); bn2[3] = *reinterpret_cast<unsigned long long*>(&p);
            }
#pragma unroll
            for (int i = 0; i < 8; i++) {
                float a = As[k][trow + i];
                unsigned long long am2;
                asm("mov.b64 %0, {%1, %1};" : "=l"(am2) : "f"(a));
#pragma unroll
                for (int j = 0; j < 4; j++) {
                    asm("fma.rn.f32x2 %0, %1, %2, %3;"
                        : "=l"(acc2[i][j])
                        : "l"(am2), "l"(bn2[j]), "l"(acc2[i][j]));
                }
            }
        }
        __syncthreads();
    }

#pragma unroll
    for (int i = 0; i < 8; i++) {
        int gr = brow + trow + i;
        if (gr < N) {
#pragma unroll
            for (int j = 0; j < 2; j++) {  // two float4 stores
                float2 p0 = *reinterpret_cast<float2*>(&acc2[i][2 * j + 0]);
                float2 p1 = *reinterpret_cast<float2*>(&acc2[i][2 * j + 1]);
                float4 v;
                v.x = p0.x + bias[tcol + 4 * j + 0];
                v.y = p0.y + bias[tcol + 4 * j + 1];
                v.z = p1.x + bias[tcol + 4 * j + 2];
                v.w = p1.y + bias[tcol + 4 * j + 3];
                *(float4*)(g_x + (long long)gr * 128 + tcol + 4 * j) = v;
            }
        }
    }
}

// ---------------------------------------------------------------------------
// Kernel 2: h1 = feat @ W1^T + b1, h2 = feat @ W2^T + b2   (one warp / node)
// ---------------------------------------------------------------------------
__global__ __launch_bounds__(256) void h_kernel(
    const float* __restrict__ feat,
    const float* __restrict__ W1, const float* __restrict__ b1,
    const float* __restrict__ W2, const float* __restrict__ b2,
    int N)
{
    int warp = (blockIdx.x * blockDim.x + threadIdx.x) >> 5;
    if (warp >= N) return;
    int lane = threadIdx.x & 31;

    float a[4] = {0.f, 0.f, 0.f, 0.f};
    float b[4] = {0.f, 0.f, 0.f, 0.f};
    const float* frow = feat + (long long)warp * 256;
#pragma unroll
    for (int kk = 0; kk < 8; kk++) {
        int k   = lane + kk * 32;
        float f = frow[k];
#pragma unroll
        for (int j = 0; j < 4; j++) {
            a[j] = fmaf(f, __ldg(W1 + j * 256 + k), a[j]);
            b[j] = fmaf(f, __ldg(W2 + j * 256 + k), b[j]);
        }
    }
#pragma unroll
    for (int off = 16; off; off >>= 1) {
#pragma unroll
        for (int j = 0; j < 4; j++) {
            a[j] += __shfl_xor_sync(0xFFFFFFFFu, a[j], off);
            b[j] += __shfl_xor_sync(0xFFFFFFFFu, b[j], off);
        }
    }
    if (lane == 0) {
        g_h1[warp] = make_float4(a[0] + b1[0], a[1] + b1[1], a[2] + b1[2], a[3] + b1[3]);
        g_h2[warp] = make_float4(b[0] + b2[0], b[1] + b2[1], b[2] + b2[2], b[3] + b2[3]);
    }
}

// ---------------------------------------------------------------------------
// CSR build: zero counts, count degrees, scan, scatter dst by src
// ---------------------------------------------------------------------------
__global__ void zero_cnt_kernel(int N)
{
    int i = blockIdx.x * blockDim.x + threadIdx.x;
    if (i < N) g_cnt[i] = 0;
}

__global__ void count_kernel(const int* __restrict__ ei, int E)
{
    int e = blockIdx.x * blockDim.x + threadIdx.x;
    if (e < E) atomicAdd(&g_cnt[ei[e]], 1);
}

__global__ __launch_bounds__(1024) void scan_kernel(int N)
{
    __shared__ int warp_sums[32];
    __shared__ int s_carry;
    const int tid = threadIdx.x, lane = tid & 31, wid = tid >> 5;
    if (tid == 0) s_carry = 0;
    __syncthreads();

    for (int base = 0; base < N; base += 1024) {
        int i = base + tid;
        int v = (i < N) ? g_cnt[i] : 0;
        int x = v;
#pragma unroll
        for (int o = 1; o < 32; o <<= 1) {
            int y = __shfl_up_sync(0xFFFFFFFFu, x, o);
            if (lane >= o) x += y;
        }
        if (lane == 31) warp_sums[wid] = x;
        __syncthreads();
        if (wid == 0) {
            int s = warp_sums[lane];
#pragma unroll
            for (int o = 1; o < 32; o <<= 1) {
                int y = __shfl_up_sync(0xFFFFFFFFu, s, o);
                if (lane >= o) s += y;
            }
            warp_sums[lane] = s;
        }
        __syncthreads();
        int warp_off = (wid == 0) ? 0 : warp_sums[wid - 1];
        int excl = s_carry + warp_off + x - v;
        if (i < N) { g_off[i] = excl; g_cur[i] = excl; }
        int chunk_total = warp_sums[31];
        __syncthreads();
        if (tid == 0) s_carry += chunk_total;
        __syncthreads();
    }
    if (tid == 0) g_off[N] = s_carry;
}

__global__ void scatter_kernel(const int* __restrict__ ei, int E)
{
    int e = blockIdx.x * blockDim.x + threadIdx.x;
    if (e < E) {
        int s = ei[e];
        int d = ei[E + e];
        int pos = atomicAdd(&g_cur[s], 1);
        g_sdst[pos] = d;
    }
}

// ---------------------------------------------------------------------------
// Kernel 4: aggregate.  One warp per node, no atomics.
//   out[n][h*32+f] = sum_{e: src=n} relu(h1[n][h]+h2[dst][h]) * x[dst][h*32+f]
//                    + eps * x[n][h*32+f]
// ---------------------------------------------------------------------------
__global__ __launch_bounds__(256) void agg_kernel(
    const float* __restrict__ eps,
    float* __restrict__ OUT,
    int N)
{
    int node = (blockIdx.x * blockDim.x + threadIdx.x) >> 5;
    if (node >= N) return;
    int lane = threadIdx.x & 31;
    int head = lane >> 3;           // 4 heads, 8 lanes each
    int j    = lane * 4;            // feature offset (float4)

    float4 ha = g_h1[node];
    float ha_h = (head < 2) ? (head == 0 ? ha.x : ha.y)
                            : (head == 2 ? ha.z : ha.w);

    int i   = g_off[node];
    int end = g_off[node + 1];

    float4 acc = make_float4(0.f, 0.f, 0.f, 0.f);

    int dst_n = (i < end) ? __ldg(&g_sdst[i]) : 0;
    while (i < end) {
        int dst = dst_n;
        int in  = i + 1;
        if (in < end) dst_n = __ldg(&g_sdst[in]);   // prefetch next dst
        float4 hb = g_h2[dst];
        float hb_h = (head < 2) ? (head == 0 ? hb.x : hb.y)
                                : (head == 2 ? hb.z : hb.w);
        float v = ha_h + hb_h;
        if (v > 0.f) {  // relu zero-skip: drop the gather entirely
            float4 xv = *(const float4*)(g_x + (long long)dst * 128 + j);
            acc.x = fmaf(v, xv.x, acc.x);
            acc.y = fmaf(v, xv.y, acc.y);
            acc.z = fmaf(v, xv.z, acc.z);
            acc.w = fmaf(v, xv.w, acc.w);
        }
        i = in;
    }

    float e0 = eps[0];
    float4 xs = *(const float4*)(g_x + (long long)node * 128 + j);
    float4 o;
    o.x = fmaf(e0, xs.x, acc.x);
    o.y = fmaf(e0, xs.y, acc.y);
    o.z = fmaf(e0, xs.z, acc.z);
    o.w = fmaf(e0, xs.w, acc.w);
    *(float4*)(OUT + (long long)node * 128 + j) = o;
}

// ---------------------------------------------------------------------------
extern "C" void kernel_launch(void* const* d_in, const int* in_sizes, int n_in,
                              void* d_out, int out_size)
{
    const float* feat  = (const float*)d_in[0];
    const int*   ei    = (const int*)d_in[1];
    const float* W_mlp = (const float*)d_in[2];
    const float* b_mlp = (const float*)d_in[3];
    const float* W1    = (const float*)d_in[4];
    const float* b1    = (const float*)d_in[5];
    const float* W2    = (const float*)d_in[6];
    const float* b2    = (const float*)d_in[7];
    const float* eps   = (const float*)d_in[8];

    const int N = in_sizes[0] / 256;
    const int E = in_sizes[1] / 2;
    float* out = (float*)d_out;

    // CSR build (by src)
    zero_cnt_kernel<<<(N + 255) / 256, 256>>>(N);
    count_kernel<<<(E + 255) / 256, 256>>>(ei, E);
    scan_kernel<<<1, 1024>>>(N);
    scatter_kernel<<<(E + 255) / 256, 256>>>(ei, E);

    // Dense phases
    gemm_mlp_kernel<<<(N + 127) / 128, 256>>>(feat, W_mlp, b_mlp, N);
    h_kernel<<<(N + 7) / 8, 256>>>(feat, W1, b1, W2, b2, N);

    // Atomic-free aggregation + epilogue
    agg_kernel<<<(N + 7) / 8, 256>>>(eps, out, N);
}

// round 4
// speedup vs baseline: 1.3353x; 1.2750x over previous
#include <cuda_runtime.h>
#include <cstdint>

// Problem sizes (fixed by the dataset; bounds for static scratch)
static constexpr int NN = 50000;
static constexpr int EE = 800000;

// Scratch (device globals: allocation-free per harness rules)
__device__ __align__(16) float g_x[(long long)NN * 128];  // mlp output [N,128]
__device__ float4 g_h1[NN];        // per-node logits, conv1 (4 heads)
__device__ float4 g_h2[NN];        // per-node logits, conv2 (4 heads)
__device__ int    g_cnt[NN];       // per-src degree
__device__ int    g_off[NN + 1];   // CSR row offsets
__device__ int    g_cur[NN];       // scatter cursors
__device__ int    g_sdst[EE];      // dst sorted by src

// ---------------------------------------------------------------------------
// Kernel 1: X = feat @ W_mlp + b_mlp  (SGEMM, packed f32x2 FMA — Blackwell FFMA2)
// BM=128, BN=128, BK=16, 256 threads, 8x8 micro-tile per thread
// ---------------------------------------------------------------------------
__global__ __launch_bounds__(256) void gemm_mlp_kernel(
    const float* __restrict__ A,     // feat [N,256]
    const float* __restrict__ B,     // W_mlp [256,128] row-major (K x N)
    const float* __restrict__ bias,  // [128]
    int N)
{
    __shared__ float As[16][128];  // transposed A tile: As[k][m]
    __shared__ float Bs[16][128];  // Bs[k][n]

    const int tid  = threadIdx.x;
    const int brow = blockIdx.x * 128;
    const int tcol = (tid & 15) * 8;   // 0..120
    const int trow = (tid >> 4) * 8;   // 0..120

    unsigned long long acc2[8][4];
#pragma unroll
    for (int i = 0; i < 8; i++)
#pragma unroll
        for (int j = 0; j < 4; j++) acc2[i][j] = 0ull;

    for (int k0 = 0; k0 < 256; k0 += 16) {
#pragma unroll
        for (int i = 0; i < 2; i++) {
            int idx = tid * 2 + i;          // 0..511
            int r   = idx >> 2;             // 0..127
            int c4  = (idx & 3) * 4;        // 0,4,8,12
            int gr  = brow + r;
            float4 v = make_float4(0.f, 0.f, 0.f, 0.f);
            if (gr < N) v = *(const float4*)(A + (long long)gr * 256 + k0 + c4);
            As[c4 + 0][r] = v.x;
            As[c4 + 1][r] = v.y;
            As[c4 + 2][r] = v.z;
            As[c4 + 3][r] = v.w;
        }
#pragma unroll
        for (int i = 0; i < 2; i++) {
            int idx = tid * 2 + i;          // 0..511
            int r   = idx >> 5;             // 0..15
            int c4  = (idx & 31) * 4;       // 0..124
            *(float4*)&Bs[r][c4] = *(const float4*)(B + (long long)(k0 + r) * 128 + c4);
        }
        __syncthreads();

#pragma unroll
        for (int k = 0; k < 16; k++) {
            unsigned long long bn2[4];
            {
                float4 b0 = *(const float4*)&Bs[k][tcol];
                float4 b1 = *(const float4*)&Bs[k][tcol + 4];
                float2 p;
                p = make_float2(b0.x, b0.y); bn2[0] = *reinterpret_cast<unsigned long long*>(&p);
                p = make_float2(b0.z, b0.w); bn2[1] = *reinterpret_cast<unsigned long long*>(&p);
                p = make_float2(b1.x, b1.y); bn2[2] = *reinterpret_cast<unsigned long long*>(&p);
                p = make_float2(b1.z, b1.w); bn2[3] = *reinterpret_cast<unsigned long long*>(&p);
            }
#pragma unroll
            for (int i = 0; i < 8; i++) {
                float a = As[k][trow + i];
                unsigned long long am2;
                asm("mov.b64 %0, {%1, %1};" : "=l"(am2) : "f"(a));
#pragma unroll
                for (int j = 0; j < 4; j++) {
                    asm("fma.rn.f32x2 %0, %1, %2, %3;"
                        : "=l"(acc2[i][j])
                        : "l"(am2), "l"(bn2[j]), "l"(acc2[i][j]));
                }
            }
        }
        __syncthreads();
    }

#pragma unroll
    for (int i = 0; i < 8; i++) {
        int gr = brow + trow + i;
        if (gr < N) {
#pragma unroll
            for (int j = 0; j < 2; j++) {
                float2 p0 = *reinterpret_cast<float2*>(&acc2[i][2 * j + 0]);
                float2 p1 = *reinterpret_cast<float2*>(&acc2[i][2 * j + 1]);
                float4 v;
                v.x = p0.x + bias[tcol + 4 * j + 0];
                v.y = p0.y + bias[tcol + 4 * j + 1];
                v.z = p1.x + bias[tcol + 4 * j + 2];
                v.w = p1.y + bias[tcol + 4 * j + 3];
                *(float4*)(g_x + (long long)gr * 128 + tcol + 4 * j) = v;
            }
        }
    }
}

// ---------------------------------------------------------------------------
// Kernel 2: h1 = feat @ W1^T + b1, h2 = feat @ W2^T + b2   (one warp / node)
// ---------------------------------------------------------------------------
__global__ __launch_bounds__(256) void h_kernel(
    const float* __restrict__ feat,
    const float* __restrict__ W1, const float* __restrict__ b1,
    const float* __restrict__ W2, const float* __restrict__ b2,
    int N)
{
    int warp = (blockIdx.x * blockDim.x + threadIdx.x) >> 5;
    if (warp >= N) return;
    int lane = threadIdx.x & 31;

    float a[4] = {0.f, 0.f, 0.f, 0.f};
    float b[4] = {0.f, 0.f, 0.f, 0.f};
    const float* frow = feat + (long long)warp * 256;
#pragma unroll
    for (int kk = 0; kk < 8; kk++) {
        int k   = lane + kk * 32;
        float f = frow[k];
#pragma unroll
        for (int j = 0; j < 4; j++) {
            a[j] = fmaf(f, __ldg(W1 + j * 256 + k), a[j]);
            b[j] = fmaf(f, __ldg(W2 + j * 256 + k), b[j]);
        }
    }
#pragma unroll
    for (int off = 16; off; off >>= 1) {
#pragma unroll
        for (int j = 0; j < 4; j++) {
            a[j] += __shfl_xor_sync(0xFFFFFFFFu, a[j], off);
            b[j] += __shfl_xor_sync(0xFFFFFFFFu, b[j], off);
        }
    }
    if (lane == 0) {
        g_h1[warp] = make_float4(a[0] + b1[0], a[1] + b1[1], a[2] + b1[2], a[3] + b1[3]);
        g_h2[warp] = make_float4(b[0] + b2[0], b[1] + b2[1], b[2] + b2[2], b[3] + b2[3]);
    }
}

// ---------------------------------------------------------------------------
// CSR build: zero counts, count degrees, scan, scatter dst by src
// ---------------------------------------------------------------------------
__global__ void zero_cnt_kernel(int N)
{
    int i = blockIdx.x * blockDim.x + threadIdx.x;
    if (i < N) g_cnt[i] = 0;
}

__global__ void count_kernel(const int* __restrict__ ei, int E)
{
    int e = blockIdx.x * blockDim.x + threadIdx.x;
    if (e < E) atomicAdd(&g_cnt[ei[e]], 1);
}

__global__ __launch_bounds__(1024) void scan_kernel(int N)
{
    __shared__ int warp_sums[32];
    __shared__ int s_carry;
    const int tid = threadIdx.x, lane = tid & 31, wid = tid >> 5;
    if (tid == 0) s_carry = 0;
    __syncthreads();

    for (int base = 0; base < N; base += 1024) {
        int i = base + tid;
        int v = (i < N) ? g_cnt[i] : 0;
        int x = v;
#pragma unroll
        for (int o = 1; o < 32; o <<= 1) {
            int y = __shfl_up_sync(0xFFFFFFFFu, x, o);
            if (lane >= o) x += y;
        }
        if (lane == 31) warp_sums[wid] = x;
        __syncthreads();
        if (wid == 0) {
            int s = warp_sums[lane];
#pragma unroll
            for (int o = 1; o < 32; o <<= 1) {
                int y = __shfl_up_sync(0xFFFFFFFFu, s, o);
                if (lane >= o) s += y;
            }
            warp_sums[lane] = s;
        }
        __syncthreads();
        int warp_off = (wid == 0) ? 0 : warp_sums[wid - 1];
        int excl = s_carry + warp_off + x - v;
        if (i < N) { g_off[i] = excl; g_cur[i] = excl; }
        int chunk_total = warp_sums[31];
        __syncthreads();
        if (tid == 0) s_carry += chunk_total;
        __syncthreads();
    }
    if (tid == 0) g_off[N] = s_carry;
}

__global__ void scatter_kernel(const int* __restrict__ ei, int E)
{
    int e = blockIdx.x * blockDim.x + threadIdx.x;
    if (e < E) {
        int s = ei[e];
        int d = ei[E + e];
        int pos = atomicAdd(&g_cur[s], 1);
        g_sdst[pos] = d;
    }
}

// ---------------------------------------------------------------------------
// Kernel 4: aggregate.  One warp per node, no atomics, 2-edge ILP.
//   out[n][h*32+f] = sum_{e: src=n} relu(h1[n][h]+h2[dst][h]) * x[dst][h*32+f]
//                    + eps * x[n][h*32+f]
// ---------------------------------------------------------------------------
__global__ __launch_bounds__(256) void agg_kernel(
    const float* __restrict__ eps,
    float* __restrict__ OUT,
    int N)
{
    int node = (blockIdx.x * blockDim.x + threadIdx.x) >> 5;
    if (node >= N) return;
    int lane = threadIdx.x & 31;
    int head = lane >> 3;           // 4 heads, 8 lanes each
    int j    = lane * 4;            // feature offset (float4)

    float4 ha = g_h1[node];
    float ha_h = (head < 2) ? (head == 0 ? ha.x : ha.y)
                            : (head == 2 ? ha.z : ha.w);

    int i   = g_off[node];
    int end = g_off[node + 1];

    float4 acc0 = make_float4(0.f, 0.f, 0.f, 0.f);
    float4 acc1 = make_float4(0.f, 0.f, 0.f, 0.f);

    // 2-edge unrolled main loop: independent h2/x load chains per edge
    for (; i + 2 <= end; i += 2) {
        int d0 = __ldg(&g_sdst[i]);
        int d1 = __ldg(&g_sdst[i + 1]);
        float4 hb0 = g_h2[d0];
        float4 hb1 = g_h2[d1];
        float v0 = ha_h + ((head < 2) ? (head == 0 ? hb0.x : hb0.y)
                                      : (head == 2 ? hb0.z : hb0.w));
        float v1 = ha_h + ((head < 2) ? (head == 0 ? hb1.x : hb1.y)
                                      : (head == 2 ? hb1.z : hb1.w));
        if (v0 > 0.f) {
            float4 xv = *(const float4*)(g_x + (long long)d0 * 128 + j);
            acc0.x = fmaf(v0, xv.x, acc0.x);
            acc0.y = fmaf(v0, xv.y, acc0.y);
            acc0.z = fmaf(v0, xv.z, acc0.z);
            acc0.w = fmaf(v0, xv.w, acc0.w);
        }
        if (v1 > 0.f) {
            float4 xv = *(const float4*)(g_x + (long long)d1 * 128 + j);
            acc1.x = fmaf(v1, xv.x, acc1.x);
            acc1.y = fmaf(v1, xv.y, acc1.y);
            acc1.z = fmaf(v1, xv.z, acc1.z);
            acc1.w = fmaf(v1, xv.w, acc1.w);
        }
    }
    if (i < end) {  // tail edge
        int d0 = __ldg(&g_sdst[i]);
        float4 hb0 = g_h2[d0];
        float v0 = ha_h + ((head < 2) ? (head == 0 ? hb0.x : hb0.y)
                                      : (head == 2 ? hb0.z : hb0.w));
        if (v0 > 0.f) {
            float4 xv = *(const float4*)(g_x + (long long)d0 * 128 + j);
            acc0.x = fmaf(v0, xv.x, acc0.x);
            acc0.y = fmaf(v0, xv.y, acc0.y);
            acc0.z = fmaf(v0, xv.z, acc0.z);
            acc0.w = fmaf(v0, xv.w, acc0.w);
        }
    }

    float e0 = eps[0];
    float4 xs = *(const float4*)(g_x + (long long)node * 128 + j);
    float4 o;
    o.x = fmaf(e0, xs.x, acc0.x + acc1.x);
    o.y = fmaf(e0, xs.y, acc0.y + acc1.y);
    o.z = fmaf(e0, xs.z, acc0.z + acc1.z);
    o.w = fmaf(e0, xs.w, acc0.w + acc1.w);
    *(float4*)(OUT + (long long)node * 128 + j) = o;
}

// ---------------------------------------------------------------------------
extern "C" void kernel_launch(void* const* d_in, const int* in_sizes, int n_in,
                              void* d_out, int out_size)
{
    const float* feat  = (const float*)d_in[0];
    const int*   ei    = (const int*)d_in[1];
    const float* W_mlp = (const float*)d_in[2];
    const float* b_mlp = (const float*)d_in[3];
    const float* W1    = (const float*)d_in[4];
    const float* b1    = (const float*)d_in[5];
    const float* W2    = (const float*)d_in[6];
    const float* b2    = (const float*)d_in[7];
    const float* eps   = (const float*)d_in[8];

    const int N = in_sizes[0] / 256;
    const int E = in_sizes[1] / 2;
    float* out = (float*)d_out;

    // One-time side stream + fork/join events (host objects, no device mem)
    static cudaStream_t s_side = nullptr;
    static cudaEvent_t  ev_fork = nullptr, ev_join = nullptr;
    if (!s_side) {
        cudaStreamCreateWithFlags(&s_side, cudaStreamNonBlocking);
        cudaEventCreateWithFlags(&ev_fork, cudaEventDisableTiming);
        cudaEventCreateWithFlags(&ev_join, cudaEventDisableTiming);
    }

    // Fork: CSR build chain on side stream, concurrent with dense chain.
    cudaEventRecord(ev_fork, 0);
    cudaStreamWaitEvent(s_side, ev_fork, 0);

    zero_cnt_kernel<<<(N + 511) / 512, 512, 0, s_side>>>(N);
    count_kernel<<<(E + 255) / 256, 256, 0, s_side>>>(ei, E);
    scan_kernel<<<1, 1024, 0, s_side>>>(N);
    scatter_kernel<<<(E + 255) / 256, 256, 0, s_side>>>(ei, E);
    cudaEventRecord(ev_join, s_side);

    // Dense chain on capture (NULL) stream.
    gemm_mlp_kernel<<<(N + 127) / 128, 256>>>(feat, W_mlp, b_mlp, N);
    h_kernel<<<(N + 7) / 8, 256>>>(feat, W1, b1, W2, b2, N);

    // Join, then atomic-free aggregation + epilogue.
    cudaStreamWaitEvent(0, ev_join, 0);
    agg_kernel<<<(N + 7) / 8, 256>>>(eps, out, N);
}